// round 17
// baseline (speedup 1.0000x reference)
#include <cuda_runtime.h>
#include <math.h>

// Problem constants
#define PN   4096
#define TT   128
#define AA   32
#define KEL  409          // int(4096 * 0.1)
#define KPAD 512          // 32 warps * 16 elites, zero-weight padded
#define INFF 1e30f

// ---------------- scratch (no allocations allowed) ----------------
__device__ float g_dists[PN];
__device__ int   g_eidx[KEL];      // elite indices, rank order (top_k order)
__device__ float g_edist[KEL];     // elite dists, rank order
__device__ int   g_sidx[KPAD];     // elite indices sorted ASCENDING BY INDEX
__device__ float g_sw[KPAD];       // weights permuted to match g_sidx
__device__ float g_scalars[2];     // [0] = ssum, [1] = 1/(ssum+1e-9)
__device__ int   g_done  = 0;      // rank-phase completion ticket
__device__ int   g_phase = 0;      // score-done flag
__device__ int   g_done2 = 0;      // stats-gate passage counter (for reset)

// =====================================================================
// Kernel A: DTW min-plus DP, one warp per problem (frozen R13 loop).
// =====================================================================
__global__ void __launch_bounds__(64) dtw_kernel(const float* __restrict__ obs) {
    const unsigned FULL = 0xffffffffu;
    int warpId = (blockIdx.x * blockDim.x + threadIdx.x) >> 5;
    int lane   = threadIdx.x & 31;
    if (warpId >= PN) return;

    const float4* cbase = (const float4*)(obs + (size_t)warpId * TT * TT);

    float v0 = INFF, v1 = INFF, v2 = INFF, v3 = INFF;
    float carry = 0.0f;

    float4 c0 = __ldcs(cbase + lane);
    float s0 = c0.x;
    float s1 = s0 + c0.y;
    float s2 = s1 + c0.z;
    float s3 = s2 + c0.w;
    {
        float sum = s3;
        #pragma unroll
        for (int off = 1; off < 32; off <<= 1) {
            float t = __shfl_up_sync(FULL, sum, off);
            if (lane >= off) sum += t;
        }
        float base0 = sum - s3;
        s0 += base0; s1 += base0; s2 += base0; s3 += base0;
        c0.x = base0;
    }
    float base = c0.x;

    float4 cn = __ldcs(cbase + 32 + lane);

    #pragma unroll 2
    for (int i = 0; i < TT; i++) {
        int nl = (i + 2 < TT) ? (i + 2) : (TT - 1);
        float4 cf = __ldcs(cbase + nl * 32 + lane);

        float ns0 = cn.x;
        float ns1 = ns0 + cn.y;
        float ns2 = ns1 + cn.z;
        float ns3 = ns2 + cn.w;

        float up  = __shfl_up_sync(FULL, v3, 1);
        float sh0 = (lane == 0) ? carry : up;

        float m0 = fminf(v0, sh0);
        float m1 = fminf(v1, v0);
        float m2 = fminf(v2, v1);
        float m3 = fminf(v3, v2);

        float t0 = m0 - base;
        float t1 = m1 - s0;
        float t2 = m2 - s1;
        float t3 = m3 - s2;

        float p0 = t0;
        float p1 = fminf(p0, t1);
        float p2 = fminf(p1, t2);
        float p3 = fminf(p2, t3);

        float nsum = ns3;
        float mn   = p3;
        #pragma unroll
        for (int off = 1; off < 32; off <<= 1) {
            float ta = __shfl_up_sync(FULL, nsum, off);
            float tb = __shfl_up_sync(FULL, mn, off);
            if (lane >= off) {
                nsum += ta;
                mn    = fminf(mn, tb);
            }
        }

        float ex = __shfl_up_sync(FULL, mn, 1);
        if (lane == 0) ex = INFF;

        float nbase = nsum - ns3;

        v0 = s0 + fminf(p0, ex);
        v1 = s1 + fminf(p1, ex);
        v2 = s2 + fminf(p2, ex);
        v3 = s3 + fminf(p3, ex);

        base = nbase;
        s0 = ns0 + nbase;
        s1 = ns1 + nbase;
        s2 = ns2 + nbase;
        s3 = ns3 + nbase;
        carry = INFF;
        cn = cf;
    }

    if (lane == 31) g_dists[warpId] = v3;
}

// =====================================================================
// Kernel F: FUSED rank + score + stats. Grid 128 x 1024 (<=148 SMs, so
// all blocks are co-resident in wave 1 -> device-side phasing is safe).
//  Phase 1 (all blocks):  rank-count top-K (1 problem/warp x 32 warps).
//  Phase 2 (last block):  softmax scores + index-sorted emission.
//  Phase 3 (all blocks):  elite-gathered weighted stats, block = t.
// Counters self-reset for deterministic graph replay.
// =====================================================================
__global__ void __launch_bounds__(1024) fused_kernel(
    const float* __restrict__ noise,   // [T, P, A]
    const float* __restrict__ means,   // [T, 1, A]
    const float* __restrict__ stds,    // [T, 1, A]
    float* __restrict__ out)           // [2, T, 1, A]
{
    const unsigned FULL = 0xffffffffu;
    int tid  = threadIdx.x;
    int lane = tid & 31;
    int warp = tid >> 5;               // 0..31

    __shared__ union {
        float sd[PN];                                  // phase 1 (16 KB)
        struct {
            float    sred[1024];
            unsigned mask[PN / 32];
            int      wordpfx[PN / 32];
        } sc;                                          // phase 2 (~5 KB)
        struct {
            float sw[KPAD];
            int   si[KPAD];
            float red1[32][33];
            float red2[32][33];
        } st;                                          // phase 3 (~12.5 KB)
    } sm;
    __shared__ int s_last;

    // ---------------- Phase 1: rank counting ----------------
    for (int i = tid; i < PN; i += 1024) sm.sd[i] = g_dists[i];
    __syncthreads();

    {
        int p = blockIdx.x * 32 + warp;        // one problem per warp
        float d = sm.sd[p];
        int cnt = 0;
        #pragma unroll 4
        for (int j = lane; j < PN; j += 32) {
            float dj = sm.sd[j];
            cnt += (dj < d) || (dj == d && j < p);
        }
        #pragma unroll
        for (int off = 16; off; off >>= 1)
            cnt += __shfl_down_sync(FULL, cnt, off);
        if (lane == 0 && cnt < KEL) {
            g_eidx[cnt]  = p;
            g_edist[cnt] = d;
        }
    }

    __threadfence();
    __syncthreads();
    if (tid == 0) s_last = (atomicAdd(&g_done, 1) == TT - 1) ? 1 : 0;
    __syncthreads();

    // ---------------- Phase 2: score (last-arriving block) ----------------
    if (s_last) {
        __threadfence();   // acquire all blocks' elite writes

        float d   = (tid < KEL) ? g_edist[tid] : INFF;
        int   idx = (tid < KEL) ? g_eidx[tid]  : 0;

        if (tid < PN / 32) sm.sc.mask[tid] = 0u;

        // min reduce (1024-wide)
        sm.sc.sred[tid] = d; __syncthreads();
        #pragma unroll
        for (int s = 512; s; s >>= 1) {
            if (tid < s) sm.sc.sred[tid] = fminf(sm.sc.sred[tid], sm.sc.sred[tid + s]);
            __syncthreads();
        }
        float mind = sm.sc.sred[0]; __syncthreads();

        float e = (tid < KEL) ? expf(0.5f * (mind - d)) : 0.0f;

        sm.sc.sred[tid] = e;
        if (tid < KEL) atomicOr(&sm.sc.mask[idx >> 5], 1u << (idx & 31));
        __syncthreads();
        #pragma unroll
        for (int s = 512; s; s >>= 1) {
            if (tid < s) sm.sc.sred[tid] += sm.sc.sred[tid + s];
            __syncthreads();
        }
        float E = sm.sc.sred[0]; __syncthreads();

        float wk = e / E;

        // exclusive popcount prefix over the 128 mask words (warp 0)
        if (tid < 32) {
            int b = tid * 4;
            int c0 = __popc(sm.sc.mask[b]);
            int c1 = __popc(sm.sc.mask[b + 1]);
            int c2 = __popc(sm.sc.mask[b + 2]);
            int c3 = __popc(sm.sc.mask[b + 3]);
            int tot = c0 + c1 + c2 + c3;
            int run = tot;
            #pragma unroll
            for (int off = 1; off < 32; off <<= 1) {
                int t = __shfl_up_sync(FULL, run, off);
                if (tid >= off) run += t;
            }
            int excl = run - tot;
            sm.sc.wordpfx[b]     = excl;
            sm.sc.wordpfx[b + 1] = excl + c0;
            sm.sc.wordpfx[b + 2] = excl + c0 + c1;
            sm.sc.wordpfx[b + 3] = excl + c0 + c1 + c2;
        }

        // ssum = sum of normalized scores (matches reference recompute)
        sm.sc.sred[tid] = (tid < KEL) ? wk : 0.0f; __syncthreads();
        #pragma unroll
        for (int s = 512; s; s >>= 1) {
            if (tid < s) sm.sc.sred[tid] += sm.sc.sred[tid + s];
            __syncthreads();
        }
        if (tid == 0) {
            float ssum = sm.sc.sred[0];
            g_scalars[0] = ssum;
            g_scalars[1] = 1.0f / (ssum + 1e-9f);
        }
        __syncthreads();

        // scatter (idx, w) to index-sorted position; zero-fill padding
        if (tid < KEL) {
            int word = idx >> 5, bit = idx & 31;
            int pos = sm.sc.wordpfx[word] + __popc(sm.sc.mask[word] & ((1u << bit) - 1u));
            g_sidx[pos] = idx;
            g_sw[pos]   = wk;
        } else if (tid < KPAD) {
            g_sw[tid]   = 0.0f;
            g_sidx[tid] = 0;
        }
        __syncthreads();

        if (tid == 0) {
            g_done = 0;                 // reset ticket for next replay
            __threadfence();            // publish score results + reset
            atomicExch(&g_phase, 1);    // release the gate
        }
    } else {
        // ---------------- gate: wait for score ----------------
        if (tid == 0) {
            while (atomicAdd(&g_phase, 0) == 0) { __nanosleep(64); }
        }
        __syncthreads();
        __threadfence();   // acquire score results
    }
    __syncthreads();

    // ---------------- Phase 3: stats (block = t) ----------------
    {
        int t = blockIdx.x;

        if (tid < KPAD) {
            sm.st.sw[tid] = g_sw[tid];
            sm.st.si[tid] = g_sidx[tid];
        }
        __syncthreads();

        int e4 = lane >> 3;          // elite-in-group: 0..3
        int a4 = (lane & 7) * 4;     // a-quad base: 0,4,..,28

        float4 mean4 = *(const float4*)(means + t * AA + a4);
        float4 std4  = *(const float4*)(stds  + t * AA + a4);
        const float* nbase = noise + (size_t)t * PN * AA;

        float S1x = 0.f, S1y = 0.f, S1z = 0.f, S1w = 0.f;
        float S2x = 0.f, S2y = 0.f, S2z = 0.f, S2w = 0.f;

        int k0 = warp * 16;
        #pragma unroll
        for (int it = 0; it < 4; it++) {
            int k  = k0 + it * 4 + e4;
            float wk = sm.st.sw[k];
            int   p  = sm.st.si[k];
            float4 x = __ldg((const float4*)(nbase + p * AA + a4));

            float xx = fminf(fmaxf(fmaf(std4.x, x.x, mean4.x), -1.f), 1.f);
            float xy = fminf(fmaxf(fmaf(std4.y, x.y, mean4.y), -1.f), 1.f);
            float xz = fminf(fmaxf(fmaf(std4.z, x.z, mean4.z), -1.f), 1.f);
            float xw = fminf(fmaxf(fmaf(std4.w, x.w, mean4.w), -1.f), 1.f);

            S1x += wk * xx;  S2x += wk * xx * xx;
            S1y += wk * xy;  S2y += wk * xy * xy;
            S1z += wk * xz;  S2z += wk * xz * xz;
            S1w += wk * xw;  S2w += wk * xw * xw;
        }

        #pragma unroll
        for (int off = 16; off >= 8; off >>= 1) {
            S1x += __shfl_down_sync(FULL, S1x, off);
            S1y += __shfl_down_sync(FULL, S1y, off);
            S1z += __shfl_down_sync(FULL, S1z, off);
            S1w += __shfl_down_sync(FULL, S1w, off);
            S2x += __shfl_down_sync(FULL, S2x, off);
            S2y += __shfl_down_sync(FULL, S2y, off);
            S2z += __shfl_down_sync(FULL, S2z, off);
            S2w += __shfl_down_sync(FULL, S2w, off);
        }

        if (lane < 8) {
            sm.st.red1[warp][a4 + 0] = S1x;  sm.st.red2[warp][a4 + 0] = S2x;
            sm.st.red1[warp][a4 + 1] = S1y;  sm.st.red2[warp][a4 + 1] = S2y;
            sm.st.red1[warp][a4 + 2] = S1z;  sm.st.red2[warp][a4 + 2] = S2z;
            sm.st.red1[warp][a4 + 3] = S1w;  sm.st.red2[warp][a4 + 3] = S2w;
        }
        __syncthreads();

        if (warp == 0) {
            float s1 = 0.0f, s2 = 0.0f;
            #pragma unroll
            for (int i = 0; i < 32; i++) { s1 += sm.st.red1[i][lane]; s2 += sm.st.red2[i][lane]; }

            float mean_ta = means[t * AA + lane];
            float W     = g_scalars[0];
            float recip = g_scalars[1];
            float mu  = s1 * recip;
            float var = fmaxf((s2 - 2.0f * mu * s1 + mu * mu * W) * recip, 0.0f);
            float sd  = fminf(fmaxf(sqrtf(var), 0.05f), 1.0f);

            out[t * AA + lane]           = 0.1f * mean_ta + 0.9f * mu;  // means_new
            out[TT * AA + t * AA + lane] = sd;                          // _std
        }
    }

    // ---------------- epilogue: reset gate for next replay ----------------
    if (tid == 0) {
        int t2 = atomicAdd(&g_done2, 1);
        if (t2 == TT - 1) {            // 128th (last) block through: safe to reset
            atomicExch(&g_phase, 0);
            g_done2 = 0;
            __threadfence();
        }
    }
}

// =====================================================================
extern "C" void kernel_launch(void* const* d_in, const int* in_sizes, int n_in,
                              void* d_out, int out_size) {
    const float* obs   = (const float*)d_in[0];  // [P, T, T]
    const float* means = (const float*)d_in[1];  // [T, 1, A]
    const float* stds  = (const float*)d_in[2];  // [T, 1, A]
    const float* noise = (const float*)d_in[3];  // [T, P, A]
    float* out = (float*)d_out;                  // [2, T, 1, A]

    dtw_kernel  <<<PN / 2, 64>>>(obs);           // 2048 CTAs x 2 warps
    fused_kernel<<<TT, 1024>>>(noise, means, stds, out);  // rank+score+stats
}